// round 4
// baseline (speedup 1.0000x reference)
#include <cuda_runtime.h>
#include <cuda_bf16.h>
#include <cstdint>

#define BB 128
#define TT 64
#define II 196
#define DD 512

// ---------------- scratch --------------------------------------------------
__device__ __align__(16) int8_t g_thi8[BB * TT * DD];
__device__ __align__(16) int8_t g_tlo8[BB * TT * DD];
__device__ __align__(16) int8_t g_ihi8[BB * II * DD];
__device__ __align__(16) int8_t g_ilo8[BB * II * DD];
__device__ float g_S[BB * BB];
__device__ unsigned g_amax_bits;

#define QMAX 16250.0f

// ---------------- stage layout (bytes); K-chunk = 128 int8 = 128 B/row -----
#define A_HI 0              // 64 rows  x 128B = 8192
#define A_LO 8192
#define B_HI 16384          // 224 rows x 128B = 28672
#define B_LO 45056
#define STAGE_SZ 73728
#define SMEM_TOTAL (2 * STAGE_SZ + 2048)   // +tail pad for benign OOB ldsm

// ---------------- PTX helpers ----------------------------------------------
__device__ __forceinline__ uint32_t smem_u32(const void* p) {
    uint32_t a;
    asm("{ .reg .u64 t; cvta.to.shared.u64 t, %1; cvt.u32.u64 %0, t; }"
        : "=r"(a) : "l"(p));
    return a;
}
__device__ __forceinline__ void cp16(uint32_t dst, const void* src) {
    asm volatile("cp.async.cg.shared.global [%0], [%1], 16;"
                 :: "r"(dst), "l"(src) : "memory");
}
#define CP_COMMIT() asm volatile("cp.async.commit_group;" ::: "memory")
#define CP_WAIT1()  asm volatile("cp.async.wait_group 1;" ::: "memory")
#define CP_WAIT0()  asm volatile("cp.async.wait_group 0;" ::: "memory")

__device__ __forceinline__ void ldsm4(uint32_t* r, uint32_t addr) {
    asm volatile("ldmatrix.sync.aligned.m8n8.x4.shared.b16 {%0,%1,%2,%3}, [%4];"
                 : "=r"(r[0]), "=r"(r[1]), "=r"(r[2]), "=r"(r[3]) : "r"(addr));
}
__device__ __forceinline__ void mma_s8(int* c, const uint32_t* a, const uint32_t* b) {
    asm volatile("mma.sync.aligned.m16n8k32.row.col.s32.s8.s8.s32 "
                 "{%0,%1,%2,%3}, {%4,%5,%6,%7}, {%8,%9}, {%0,%1,%2,%3};"
                 : "+r"(c[0]), "+r"(c[1]), "+r"(c[2]), "+r"(c[3])
                 : "r"(a[0]), "r"(a[1]), "r"(a[2]), "r"(a[3]),
                   "r"(b[0]), "r"(b[1]));
}
__device__ __forceinline__ uint32_t swz(int row, uint32_t kb) {
    return (uint32_t)row * 128u + (kb ^ (uint32_t)((row & 7) << 4));
}

// ---------------- absmax reduction -----------------------------------------
__global__ void init_amax() { g_amax_bits = 0; }

__global__ __launch_bounds__(256)
void absmax_kernel(const float* __restrict__ src, int n4)
{
    float m = 0.0f;
    for (int i = blockIdx.x * 256 + threadIdx.x; i < n4; i += gridDim.x * 256) {
        float4 v = reinterpret_cast<const float4*>(src)[i];
        m = fmaxf(m, fmaxf(fmaxf(fabsf(v.x), fabsf(v.y)),
                           fmaxf(fabsf(v.z), fabsf(v.w))));
    }
    #pragma unroll
    for (int o = 16; o >= 1; o >>= 1)
        m = fmaxf(m, __shfl_xor_sync(0xffffffffu, m, o));
    if ((threadIdx.x & 31) == 0)
        atomicMax(&g_amax_bits, __float_as_uint(m));
}

// ---------------- quantize: fp32 -> (hi, lo) s8 pair (16-bit fixed pt) -----
__device__ __forceinline__ void q1(float x, float S, int& h, int& l) {
    int X = __float2int_rn(x * S);
    X = max(-16250, min(16250, X));
    h = (X + 64) >> 7;           // round-half-up to nearest 128
    l = X - (h << 7);            // in [-64, 63]
}

__global__ __launch_bounds__(256)
void quant_kernel(const float* __restrict__ src, int8_t* __restrict__ hi,
                  int8_t* __restrict__ lo, int n4)
{
    int i = blockIdx.x * 256 + threadIdx.x;
    if (i >= n4) return;
    float S = QMAX / __uint_as_float(g_amax_bits);
    float4 v = reinterpret_cast<const float4*>(src)[i];
    int h0, l0, h1, l1, h2, l2, h3, l3;
    q1(v.x, S, h0, l0); q1(v.y, S, h1, l1);
    q1(v.z, S, h2, l2); q1(v.w, S, h3, l3);
    uint32_t ph = (h0 & 255) | ((h1 & 255) << 8) | ((h2 & 255) << 16) | ((uint32_t)(h3 & 255) << 24);
    uint32_t pl = (l0 & 255) | ((l1 & 255) << 8) | ((l2 & 255) << 16) | ((uint32_t)(l3 & 255) << 24);
    reinterpret_cast<uint32_t*>(hi)[i] = ph;
    reinterpret_cast<uint32_t*>(lo)[i] = pl;
}

// ---------------- stage loader ----------------------------------------------
__device__ __forceinline__ void issue_stage(uint32_t sb,
    const int8_t* Ah, const int8_t* Al, const int8_t* Bh, const int8_t* Bl,
    int k0, int tid)
{
    #pragma unroll
    for (int q = 0; q < 2; q++) {                 // A: 64 rows x 8 segs(16B)
        int u = tid + q * 256;
        int row = u >> 3, seg = u & 7;
        uint32_t o = swz(row, seg * 16);
        size_t g = (size_t)row * DD + k0 + seg * 16;
        cp16(sb + A_HI + o, Ah + g);
        cp16(sb + A_LO + o, Al + g);
    }
    #pragma unroll
    for (int q = 0; q < 7; q++) {                 // B: 196 rows x 8 segs
        int u = tid + q * 256;
        if (u < II * 8) {
            int row = u >> 3, seg = u & 7;
            uint32_t o = swz(row, seg * 16);
            size_t g = (size_t)row * DD + k0 + seg * 16;
            cp16(sb + B_HI + o, Bh + g);
            cp16(sb + B_LO + o, Bl + g);
        }
    }
}

// ---------------- per-chunk int8 MMA compute --------------------------------
__device__ __forceinline__ void compute_chunk(uint32_t sb, int* chh, int* ccr,
                                              int wr, int wc, int lane)
{
    const int rowA0 = wr * 32 + (lane & 15);
    const uint32_t kAh = (uint32_t)(lane & 16);        // 0 or 16 bytes
    const int rowB0 = wc * 56 + ((lane & 16) ? 8 : 0) + (lane & 7);
    const uint32_t kBh = (lane & 8) ? 16u : 0u;

    #pragma unroll
    for (int s = 0; s < 4; s++) {                      // 4 k32 steps (32B each)
        uint32_t aH[8], aL[8];
        #pragma unroll
        for (int mt = 0; mt < 2; mt++) {
            uint32_t o = swz(rowA0 + mt * 16, s * 32 + kAh);
            ldsm4(aH + 4 * mt, sb + A_HI + o);
            ldsm4(aL + 4 * mt, sb + A_LO + o);
        }
        uint32_t bH[16], bL[16];
        #pragma unroll
        for (int p = 0; p < 4; p++) {
            uint32_t o = swz(rowB0 + p * 16, s * 32 + kBh);
            ldsm4(bH + 4 * p, sb + B_HI + o);
            ldsm4(bL + 4 * p, sb + B_LO + o);
        }
        #pragma unroll
        for (int mt = 0; mt < 2; mt++)
            #pragma unroll
            for (int nt = 0; nt < 7; nt++) {
                int* hh = chh + (mt * 7 + nt) * 4;
                int* cc = ccr + (mt * 7 + nt) * 4;
                mma_s8(hh, aH + 4 * mt, bH + 2 * nt);
                mma_s8(cc, aH + 4 * mt, bL + 2 * nt);
                mma_s8(cc, aL + 4 * mt, bH + 2 * nt);
            }
    }
}

// ---------------- main maxsim kernel ----------------------------------------
__global__ __launch_bounds__(256, 1)
void maxsim_mma_kernel()
{
    extern __shared__ __align__(1024) char smem[];
    const uint32_t sb = smem_u32(smem);
    const int tid  = threadIdx.x;
    const int lane = tid & 31;
    const int wid  = tid >> 5;
    const int wr   = wid >> 2;      // 0..1 : M strip of 32
    const int wc   = wid & 3;       // 0..3 : N strip of 56

    const int b1 = blockIdx.x;      // text batch
    const int b2 = blockIdx.y;      // image batch
    const int8_t* Ah = g_thi8 + (size_t)b1 * (TT * DD);
    const int8_t* Al = g_tlo8 + (size_t)b1 * (TT * DD);
    const int8_t* Bh = g_ihi8 + (size_t)b2 * (II * DD);
    const int8_t* Bl = g_ilo8 + (size_t)b2 * (II * DD);

    // zero B pad rows (196..223) in both stages, hi+lo
    {
        uint4 z = make_uint4(0, 0, 0, 0);
        for (int u = tid; u < 28 * 8; u += 256) {
            int row = 196 + (u >> 3), seg = u & 7;
            uint32_t o = swz(row, seg * 16);
            *(uint4*)(smem + B_HI + o) = z;
            *(uint4*)(smem + B_LO + o) = z;
            *(uint4*)(smem + STAGE_SZ + B_HI + o) = z;
            *(uint4*)(smem + STAGE_SZ + B_LO + o) = z;
        }
    }
    __syncthreads();

    issue_stage(sb,            Ah, Al, Bh, Bl, 0,   tid); CP_COMMIT();
    issue_stage(sb + STAGE_SZ, Ah, Al, Bh, Bl, 128, tid); CP_COMMIT();

    int chh[56], ccr[56];
    #pragma unroll
    for (int i = 0; i < 56; i++) { chh[i] = 0; ccr[i] = 0; }

    #pragma unroll 1
    for (int ck = 0; ck < 4; ck++) {
        if (ck < 3) CP_WAIT1(); else CP_WAIT0();
        __syncthreads();
        compute_chunk(sb + (ck & 1) * STAGE_SZ, chh, ccr, wr, wc, lane);
        __syncthreads();
        if (ck < 2) {
            issue_stage(sb + (ck & 1) * STAGE_SZ, Ah, Al, Bh, Bl, (ck + 2) * 128, tid);
            CP_COMMIT();
        }
    }

    // -------- epilogue: combine, masked max over i, mean over tokens --------
    float* red = (float*)smem;                 // [64][5]
    #pragma unroll
    for (int mt = 0; mt < 2; mt++) {
        float m0 = -3.0e38f, m1 = -3.0e38f;
        #pragma unroll
        for (int nt = 0; nt < 7; nt++) {
            int base = (mt * 7 + nt) * 4;
            int i0 = wc * 56 + nt * 8 + 2 * (lane & 3);
            float v0 = fmaf(16384.f, (float)chh[base + 0], 128.f * (float)ccr[base + 0]);
            float v1 = fmaf(16384.f, (float)chh[base + 1], 128.f * (float)ccr[base + 1]);
            float v2 = fmaf(16384.f, (float)chh[base + 2], 128.f * (float)ccr[base + 2]);
            float v3 = fmaf(16384.f, (float)chh[base + 3], 128.f * (float)ccr[base + 3]);
            if (i0 < II)     { m0 = fmaxf(m0, v0); m1 = fmaxf(m1, v2); }
            if (i0 + 1 < II) { m0 = fmaxf(m0, v1); m1 = fmaxf(m1, v3); }
        }
        #pragma unroll
        for (int o = 1; o <= 2; o <<= 1) {
            m0 = fmaxf(m0, __shfl_xor_sync(0xffffffffu, m0, o));
            m1 = fmaxf(m1, __shfl_xor_sync(0xffffffffu, m1, o));
        }
        if ((lane & 3) == 0) {
            int t = wr * 32 + mt * 16 + (lane >> 2);
            red[t * 5 + wc]       = m0;
            red[(t + 8) * 5 + wc] = m1;
        }
    }
    __syncthreads();
    float* red2 = red + 512;
    if (tid < 64) {
        float m = fmaxf(fmaxf(red[tid * 5 + 0], red[tid * 5 + 1]),
                        fmaxf(red[tid * 5 + 2], red[tid * 5 + 3]));
        red2[tid] = m;
    }
    __syncthreads();
    if (wid == 0) {
        float v = red2[lane] + red2[lane + 32];
        #pragma unroll
        for (int o = 16; o >= 1; o >>= 1) v += __shfl_xor_sync(0xffffffffu, v, o);
        if (lane == 0) {
            float S = QMAX / __uint_as_float(g_amax_bits);
            g_S[b1 * BB + b2] = v / (S * S * 64.0f);
        }
    }
}

// ---------------- loss kernel ----------------------------------------------
__global__ __launch_bounds__(256)
void loss_kernel(float* __restrict__ out)
{
    extern __shared__ float sh[];                 // [128][129]
    __shared__ float ws[8];
    const int tid = threadIdx.x;
    const float invT = 1.0f / 0.07f;

    for (int i = tid; i < BB * 32; i += 256) {
        int b = i >> 5, j4 = i & 31;
        float4 v = reinterpret_cast<const float4*>(g_S)[b * 32 + j4];
        float* row = sh + b * 129 + j4 * 4;
        row[0] = v.x; row[1] = v.y; row[2] = v.z; row[3] = v.w;
    }
    __syncthreads();

    const int b = tid & 127;
    const bool isCol = tid >= 128;
    float mx = -3.0e38f;
    #pragma unroll 4
    for (int j = 0; j < BB; j++) {
        float v = (isCol ? sh[j * 129 + b] : sh[b * 129 + j]) * invT;
        mx = fmaxf(mx, v);
    }
    float s = 0.0f;
    #pragma unroll 4
    for (int j = 0; j < BB; j++) {
        float v = (isCol ? sh[j * 129 + b] : sh[b * 129 + j]) * invT;
        s += __expf(v - mx);
    }
    float lse = mx + __logf(s);
    float part = 0.5f * lse;
    if (!isCol) part -= sh[b * 129 + b] * invT;

    #pragma unroll
    for (int o = 16; o >= 1; o >>= 1) part += __shfl_xor_sync(0xffffffffu, part, o);
    if ((tid & 31) == 0) ws[tid >> 5] = part;
    __syncthreads();
    if (tid == 0) {
        float t = 0.0f;
        #pragma unroll
        for (int w = 0; w < 8; w++) t += ws[w];
        out[0] = t * (1.0f / BB);
    }
}

// ---------------- launch ----------------------------------------------------
extern "C" void kernel_launch(void* const* d_in, const int* in_sizes, int n_in,
                              void* d_out, int out_size)
{
    const float* a0 = (const float*)d_in[0];
    const float* a1 = (const float*)d_in[1];
    const float *img, *txt;
    if (in_sizes[0] == BB * II * DD) { img = a0; txt = a1; }
    else                             { img = a1; txt = a0; }

    cudaFuncSetAttribute(maxsim_mma_kernel,
                         cudaFuncAttributeMaxDynamicSharedMemorySize, SMEM_TOTAL);
    cudaFuncSetAttribute(loss_kernel,
                         cudaFuncAttributeMaxDynamicSharedMemorySize, 129 * 128 * 4);

    int8_t *thi, *tlo, *ihi, *ilo;
    cudaGetSymbolAddress((void**)&thi, g_thi8);
    cudaGetSymbolAddress((void**)&tlo, g_tlo8);
    cudaGetSymbolAddress((void**)&ihi, g_ihi8);
    cudaGetSymbolAddress((void**)&ilo, g_ilo8);

    const int nt4 = BB * TT * DD / 4;
    const int ni4 = BB * II * DD / 4;

    init_amax<<<1, 1>>>();
    absmax_kernel<<<1024, 256>>>(txt, nt4);
    absmax_kernel<<<1024, 256>>>(img, ni4);
    quant_kernel<<<(nt4 + 255) / 256, 256>>>(txt, thi, tlo, nt4);
    quant_kernel<<<(ni4 + 255) / 256, 256>>>(img, ihi, ilo, ni4);

    dim3 grid(BB, BB);   // 128 x 128
    maxsim_mma_kernel<<<grid, 256, SMEM_TOTAL>>>();

    loss_kernel<<<1, 256, 129 * 128 * 4>>>((float*)d_out);
}

// round 5
// speedup vs baseline: 4.6500x; 4.6500x over previous
#include <cuda_runtime.h>
#include <cuda_fp16.h>
#include <cstdint>

#define BB 128
#define TT 64
#define II 196
#define DD 512

// ---------------- scratch --------------------------------------------------
__device__ __align__(16) __half g_thi[BB * TT * DD];
__device__ __align__(16) __half g_tlo[BB * TT * DD];
__device__ __align__(16) __half g_img[BB * II * DD];
__device__ float g_S[BB * BB];

// ---------------- stage layout (bytes); K-chunk = 64 halves = 128 B/row ----
#define A_HI 0              // 128 rows x 128B = 16384
#define A_LO 16384
#define B_T  32768          // 224 rows x 128B = 28672
#define STAGE_SZ 61440
#define SMEM_TOTAL (2 * STAGE_SZ + 2048)   // 124928

// ---------------- PTX helpers ----------------------------------------------
__device__ __forceinline__ uint32_t smem_u32(const void* p) {
    uint32_t a;
    asm("{ .reg .u64 t; cvta.to.shared.u64 t, %1; cvt.u32.u64 %0, t; }"
        : "=r"(a) : "l"(p));
    return a;
}
__device__ __forceinline__ void cp16(uint32_t dst, const void* src) {
    asm volatile("cp.async.cg.shared.global [%0], [%1], 16;"
                 :: "r"(dst), "l"(src) : "memory");
}
#define CP_COMMIT() asm volatile("cp.async.commit_group;" ::: "memory")
#define CP_WAIT1()  asm volatile("cp.async.wait_group 1;" ::: "memory")
#define CP_WAIT0()  asm volatile("cp.async.wait_group 0;" ::: "memory")

__device__ __forceinline__ void ldsm4(uint32_t* r, uint32_t addr) {
    asm volatile("ldmatrix.sync.aligned.m8n8.x4.shared.b16 {%0,%1,%2,%3}, [%4];"
                 : "=r"(r[0]), "=r"(r[1]), "=r"(r[2]), "=r"(r[3]) : "r"(addr));
}
__device__ __forceinline__ void mma_f16(float* c, const uint32_t* a, const uint32_t* b) {
    asm volatile("mma.sync.aligned.m16n8k16.row.col.f32.f16.f16.f32 "
                 "{%0,%1,%2,%3}, {%4,%5,%6,%7}, {%8,%9}, {%0,%1,%2,%3};"
                 : "+f"(c[0]), "+f"(c[1]), "+f"(c[2]), "+f"(c[3])
                 : "r"(a[0]), "r"(a[1]), "r"(a[2]), "r"(a[3]),
                   "r"(b[0]), "r"(b[1]));
}
__device__ __forceinline__ uint32_t swz(int row, uint32_t kb) {
    return (uint32_t)row * 128u + (kb ^ (uint32_t)((row & 7) << 4));
}

// ---------------- split kernels ---------------------------------------------
__global__ __launch_bounds__(256)
void split_text_kernel(const float* __restrict__ src, __half* __restrict__ hi,
                       __half* __restrict__ lo, int n4)
{
    int i = blockIdx.x * 256 + threadIdx.x;
    if (i >= n4) return;
    float4 v = reinterpret_cast<const float4*>(src)[i];
    __half h0 = __float2half(v.x), h1 = __float2half(v.y);
    __half h2 = __float2half(v.z), h3 = __float2half(v.w);
    __half l0 = __float2half(v.x - __half2float(h0));
    __half l1 = __float2half(v.y - __half2float(h1));
    __half l2 = __float2half(v.z - __half2float(h2));
    __half l3 = __float2half(v.w - __half2float(h3));
    __half2 hA(h0, h1), hB(h2, h3), lA(l0, l1), lB(l2, l3);
    uint2 uh, ul;
    uh.x = *(uint32_t*)&hA; uh.y = *(uint32_t*)&hB;
    ul.x = *(uint32_t*)&lA; ul.y = *(uint32_t*)&lB;
    reinterpret_cast<uint2*>(hi)[i] = uh;
    reinterpret_cast<uint2*>(lo)[i] = ul;
}

__global__ __launch_bounds__(256)
void round_img_kernel(const float* __restrict__ src, __half* __restrict__ dst, int n4)
{
    int i = blockIdx.x * 256 + threadIdx.x;
    if (i >= n4) return;
    float4 v = reinterpret_cast<const float4*>(src)[i];
    __half2 a(__float2half(v.x), __float2half(v.y));
    __half2 b(__float2half(v.z), __float2half(v.w));
    uint2 u;
    u.x = *(uint32_t*)&a; u.y = *(uint32_t*)&b;
    reinterpret_cast<uint2*>(dst)[i] = u;
}

// ---------------- stage loader ----------------------------------------------
__device__ __forceinline__ void issue_stage(uint32_t sb,
    const __half* Ah, const __half* Al, const __half* Bt, int k0, int tid)
{
    #pragma unroll
    for (int q = 0; q < 4; q++) {                 // A: 128 rows x 8 segs(16B)
        int u = tid + q * 256;
        int row = u >> 3, seg = u & 7;
        uint32_t o = swz(row, seg * 16);
        size_t g = (size_t)row * DD + k0 + seg * 8;
        cp16(sb + A_HI + o, Ah + g);
        cp16(sb + A_LO + o, Al + g);
    }
    #pragma unroll
    for (int q = 0; q < 7; q++) {                 // B: 196 rows x 8 segs
        int u = tid + q * 256;
        if (u < II * 8) {
            int row = u >> 3, seg = u & 7;
            uint32_t o = swz(row, seg * 16);
            size_t g = (size_t)row * DD + k0 + seg * 8;
            cp16(sb + B_T + o, Bt + g);
        }
    }
}

// ---------------- per-chunk compute: (Ah + Al) x Bh -------------------------
__device__ __forceinline__ void compute_chunk(uint32_t sb, float* c,
                                              int wr, int wc, int lane)
{
    const int rowA0 = wr * 32 + (lane & 15);
    const uint32_t kAh = (lane & 16) ? 16u : 0u;
    const int rowB0 = wc * 112 + ((lane & 16) ? 8 : 0) + (lane & 7);
    const uint32_t kBh = (lane & 8) ? 16u : 0u;

    #pragma unroll
    for (int s = 0; s < 4; s++) {
        uint32_t aH[8], aL[8];
        #pragma unroll
        for (int mt = 0; mt < 2; mt++) {
            uint32_t o = swz(rowA0 + mt * 16, s * 32 + kAh);
            ldsm4(aH + 4 * mt, sb + A_HI + o);
            ldsm4(aL + 4 * mt, sb + A_LO + o);
        }
        uint32_t b[28];
        #pragma unroll
        for (int p = 0; p < 7; p++) {
            uint32_t o = swz(rowB0 + p * 16, s * 32 + kBh);
            ldsm4(b + 4 * p, sb + B_T + o);
        }
        #pragma unroll
        for (int mt = 0; mt < 2; mt++)
            #pragma unroll
            for (int nt = 0; nt < 14; nt++) {
                float* acc = c + (mt * 14 + nt) * 4;
                mma_f16(acc, aH + 4 * mt, b + 2 * nt);
                mma_f16(acc, aL + 4 * mt, b + 2 * nt);
            }
    }
}

// ---------------- main maxsim kernel ----------------------------------------
__global__ __launch_bounds__(256, 1)
void maxsim_mma_kernel()
{
    extern __shared__ __align__(1024) char smem[];
    const uint32_t sb = smem_u32(smem);
    const int tid  = threadIdx.x;
    const int lane = tid & 31;
    const int wid  = tid >> 5;
    const int wr   = wid >> 1;      // 0..3 : M strip of 32
    const int wc   = wid & 1;       // 0..1 : N strip of 112

    const int bx = blockIdx.x;      // text pair -> batches 2bx, 2bx+1
    const int b2 = blockIdx.y;      // image batch
    const __half* Ah = g_thi + (size_t)bx * (2 * TT * DD);
    const __half* Al = g_tlo + (size_t)bx * (2 * TT * DD);
    const __half* Bt = g_img + (size_t)b2 * (II * DD);

    // zero B pad rows (196..223) in both stages
    {
        uint4 z = make_uint4(0, 0, 0, 0);
        for (int u = tid; u < 28 * 8; u += 256) {
            int row = 196 + (u >> 3), seg = u & 7;
            uint32_t o = swz(row, seg * 16);
            *(uint4*)(smem + B_T + o) = z;
            *(uint4*)(smem + STAGE_SZ + B_T + o) = z;
        }
    }
    __syncthreads();

    issue_stage(sb,            Ah, Al, Bt, 0,  tid); CP_COMMIT();
    issue_stage(sb + STAGE_SZ, Ah, Al, Bt, 64, tid); CP_COMMIT();

    float c[112];
    #pragma unroll
    for (int i = 0; i < 112; i++) c[i] = 0.0f;

    #pragma unroll 1
    for (int ck = 0; ck < 8; ck++) {
        if (ck < 7) CP_WAIT1(); else CP_WAIT0();
        __syncthreads();
        compute_chunk(sb + (ck & 1) * STAGE_SZ, c, wr, wc, lane);
        __syncthreads();
        if (ck < 6) {
            issue_stage(sb + (ck & 1) * STAGE_SZ, Ah, Al, Bt, (ck + 2) * 64, tid);
            CP_COMMIT();
        }
    }

    // ---------------- epilogue: masked row-max, then mean over tokens -------
    float* red = (float*)smem;      // [2][128] then [128] scratch
    #pragma unroll
    for (int mt = 0; mt < 2; mt++) {
        float m0 = -3.0e38f, m1 = -3.0e38f;
        #pragma unroll
        for (int nt = 0; nt < 14; nt++) {
            const float* acc = c + (mt * 14 + nt) * 4;
            int i0 = wc * 112 + nt * 8 + 2 * (lane & 3);
            if (i0 < II)     { m0 = fmaxf(m0, acc[0]); m1 = fmaxf(m1, acc[2]); }
            if (i0 + 1 < II) { m0 = fmaxf(m0, acc[1]); m1 = fmaxf(m1, acc[3]); }
        }
        #pragma unroll
        for (int o = 1; o <= 2; o <<= 1) {
            m0 = fmaxf(m0, __shfl_xor_sync(0xffffffffu, m0, o));
            m1 = fmaxf(m1, __shfl_xor_sync(0xffffffffu, m1, o));
        }
        if ((lane & 3) == 0) {
            int t = wr * 32 + mt * 16 + (lane >> 2);
            red[wc * 128 + t]     = m0;
            red[wc * 128 + t + 8] = m1;
        }
    }
    __syncthreads();
    float* red2 = red + 256;
    if (tid < 128) red2[tid] = fmaxf(red[tid], red[128 + tid]);
    __syncthreads();
    if (wid < 2) {
        float v = red2[wid * 64 + lane] + red2[wid * 64 + 32 + lane];
        #pragma unroll
        for (int o = 16; o >= 1; o >>= 1) v += __shfl_xor_sync(0xffffffffu, v, o);
        if (lane == 0) g_S[(2 * bx + wid) * BB + b2] = v * (1.0f / 64.0f);
    }
}

// ---------------- loss kernel ----------------------------------------------
__global__ __launch_bounds__(256)
void loss_kernel(float* __restrict__ out)
{
    extern __shared__ float sh[];                 // [128][129]
    __shared__ float ws[8];
    const int tid = threadIdx.x;
    const float invT = 1.0f / 0.07f;

    for (int i = tid; i < BB * 32; i += 256) {
        int b = i >> 5, j4 = i & 31;
        float4 v = reinterpret_cast<const float4*>(g_S)[b * 32 + j4];
        float* row = sh + b * 129 + j4 * 4;
        row[0] = v.x; row[1] = v.y; row[2] = v.z; row[3] = v.w;
    }
    __syncthreads();

    const int b = tid & 127;
    const bool isCol = tid >= 128;
    float mx = -3.0e38f;
    #pragma unroll 4
    for (int j = 0; j < BB; j++) {
        float v = (isCol ? sh[j * 129 + b] : sh[b * 129 + j]) * invT;
        mx = fmaxf(mx, v);
    }
    float s = 0.0f;
    #pragma unroll 4
    for (int j = 0; j < BB; j++) {
        float v = (isCol ? sh[j * 129 + b] : sh[b * 129 + j]) * invT;
        s += __expf(v - mx);
    }
    float lse = mx + __logf(s);
    float part = 0.5f * lse;
    if (!isCol) part -= sh[b * 129 + b] * invT;

    #pragma unroll
    for (int o = 16; o >= 1; o >>= 1) part += __shfl_xor_sync(0xffffffffu, part, o);
    if ((tid & 31) == 0) ws[tid >> 5] = part;
    __syncthreads();
    if (tid == 0) {
        float t = 0.0f;
        #pragma unroll
        for (int w = 0; w < 8; w++) t += ws[w];
        out[0] = t * (1.0f / BB);
    }
}

// ---------------- launch ----------------------------------------------------
extern "C" void kernel_launch(void* const* d_in, const int* in_sizes, int n_in,
                              void* d_out, int out_size)
{
    const float* a0 = (const float*)d_in[0];
    const float* a1 = (const float*)d_in[1];
    const float *img, *txt;
    if (in_sizes[0] == BB * II * DD) { img = a0; txt = a1; }
    else                             { img = a1; txt = a0; }

    cudaFuncSetAttribute(maxsim_mma_kernel,
                         cudaFuncAttributeMaxDynamicSharedMemorySize, SMEM_TOTAL);
    cudaFuncSetAttribute(loss_kernel,
                         cudaFuncAttributeMaxDynamicSharedMemorySize, 129 * 128 * 4);

    __half *thi, *tlo, *ih;
    cudaGetSymbolAddress((void**)&thi, g_thi);
    cudaGetSymbolAddress((void**)&tlo, g_tlo);
    cudaGetSymbolAddress((void**)&ih,  g_img);

    const int nt4 = BB * TT * DD / 4;
    const int ni4 = BB * II * DD / 4;
    split_text_kernel<<<(nt4 + 255) / 256, 256>>>(txt, thi, tlo, nt4);
    round_img_kernel<<<(ni4 + 255) / 256, 256>>>(img, ih, ni4);

    dim3 grid(BB / 2, BB);   // 64 x 128
    maxsim_mma_kernel<<<grid, 256, SMEM_TOTAL>>>();

    loss_kernel<<<1, 256, 129 * 128 * 4>>>((float*)d_out);
}

// round 6
// speedup vs baseline: 7.7518x; 1.6670x over previous
#include <cuda_runtime.h>
#include <cuda_fp16.h>
#include <cstdint>

#define BB 128
#define TT 64
#define II 196
#define DD 512

// ---------------- scratch --------------------------------------------------
__device__ __align__(16) __half g_txt[BB * TT * DD];
__device__ __align__(16) __half g_img[BB * II * DD];
__device__ float g_S[BB * BB];

// ---------------- stage layout (bytes); K-chunk = 64 halves = 128 B/row ----
#define A_T  0              // 128 rows x 128B = 16384
#define B_T  16384          // 224 rows x 128B = 28672
#define STAGE_SZ 45056
#define N_STAGE 3
#define SMEM_TOTAL (N_STAGE * STAGE_SZ + 2048)   // 137216

// ---------------- PTX helpers ----------------------------------------------
__device__ __forceinline__ uint32_t smem_u32(const void* p) {
    uint32_t a;
    asm("{ .reg .u64 t; cvta.to.shared.u64 t, %1; cvt.u32.u64 %0, t; }"
        : "=r"(a) : "l"(p));
    return a;
}
__device__ __forceinline__ void cp16(uint32_t dst, const void* src) {
    asm volatile("cp.async.cg.shared.global [%0], [%1], 16;"
                 :: "r"(dst), "l"(src) : "memory");
}
#define CP_COMMIT() asm volatile("cp.async.commit_group;" ::: "memory")
#define CP_WAIT2()  asm volatile("cp.async.wait_group 2;" ::: "memory")
#define CP_WAIT1()  asm volatile("cp.async.wait_group 1;" ::: "memory")
#define CP_WAIT0()  asm volatile("cp.async.wait_group 0;" ::: "memory")

__device__ __forceinline__ void ldsm4(uint32_t* r, uint32_t addr) {
    asm volatile("ldmatrix.sync.aligned.m8n8.x4.shared.b16 {%0,%1,%2,%3}, [%4];"
                 : "=r"(r[0]), "=r"(r[1]), "=r"(r[2]), "=r"(r[3]) : "r"(addr));
}
__device__ __forceinline__ void mma_f16(float* c, const uint32_t* a, const uint32_t* b) {
    asm volatile("mma.sync.aligned.m16n8k16.row.col.f32.f16.f16.f32 "
                 "{%0,%1,%2,%3}, {%4,%5,%6,%7}, {%8,%9}, {%0,%1,%2,%3};"
                 : "+f"(c[0]), "+f"(c[1]), "+f"(c[2]), "+f"(c[3])
                 : "r"(a[0]), "r"(a[1]), "r"(a[2]), "r"(a[3]),
                   "r"(b[0]), "r"(b[1]));
}
__device__ __forceinline__ uint32_t swz(int row, uint32_t kb) {
    return (uint32_t)row * 128u + (kb ^ (uint32_t)((row & 7) << 4));
}

// ---------------- round kernel: fp32 -> fp16 --------------------------------
__global__ __launch_bounds__(256)
void round_kernel(const float* __restrict__ src, __half* __restrict__ dst, int n4)
{
    int i = blockIdx.x * 256 + threadIdx.x;
    if (i >= n4) return;
    float4 v = reinterpret_cast<const float4*>(src)[i];
    __half2 a(__float2half(v.x), __float2half(v.y));
    __half2 b(__float2half(v.z), __float2half(v.w));
    uint2 u;
    u.x = *(uint32_t*)&a; u.y = *(uint32_t*)&b;
    reinterpret_cast<uint2*>(dst)[i] = u;
}

// ---------------- stage loader ----------------------------------------------
__device__ __forceinline__ void issue_stage(uint32_t sb,
    const __half* At, const __half* Bt, int k0, int tid)
{
    #pragma unroll
    for (int q = 0; q < 4; q++) {                 // A: 128 rows x 8 segs(16B)
        int u = tid + q * 256;
        int row = u >> 3, seg = u & 7;
        uint32_t o = swz(row, seg * 16);
        size_t g = (size_t)row * DD + k0 + seg * 8;
        cp16(sb + A_T + o, At + g);
    }
    #pragma unroll
    for (int q = 0; q < 7; q++) {                 // B: 196 rows x 8 segs
        int u = tid + q * 256;
        if (u < II * 8) {
            int row = u >> 3, seg = u & 7;
            uint32_t o = swz(row, seg * 16);
            size_t g = (size_t)row * DD + k0 + seg * 8;
            cp16(sb + B_T + o, Bt + g);
        }
    }
}

// ---------------- per-chunk compute: A x B (single fp16 pass) ---------------
__device__ __forceinline__ void compute_chunk(uint32_t sb, float* c,
                                              int wr, int wc, int lane)
{
    const int rowA0 = wr * 32 + (lane & 15);
    const uint32_t kAh = (lane & 16) ? 16u : 0u;
    const int rowB0 = wc * 112 + ((lane & 16) ? 8 : 0) + (lane & 7);
    const uint32_t kBh = (lane & 8) ? 16u : 0u;

    #pragma unroll
    for (int s = 0; s < 4; s++) {
        uint32_t a[8];
        #pragma unroll
        for (int mt = 0; mt < 2; mt++) {
            uint32_t o = swz(rowA0 + mt * 16, s * 32 + kAh);
            ldsm4(a + 4 * mt, sb + A_T + o);
        }
        uint32_t b[28];
        #pragma unroll
        for (int p = 0; p < 7; p++) {
            uint32_t o = swz(rowB0 + p * 16, s * 32 + kBh);
            ldsm4(b + 4 * p, sb + B_T + o);
        }
        #pragma unroll
        for (int mt = 0; mt < 2; mt++)
            #pragma unroll
            for (int nt = 0; nt < 14; nt++)
                mma_f16(c + (mt * 14 + nt) * 4, a + 4 * mt, b + 2 * nt);
    }
}

// ---------------- main maxsim kernel ----------------------------------------
__global__ __launch_bounds__(256, 1)
void maxsim_mma_kernel()
{
    extern __shared__ __align__(1024) char smem[];
    const uint32_t sb = smem_u32(smem);
    const int tid  = threadIdx.x;
    const int lane = tid & 31;
    const int wid  = tid >> 5;
    const int wr   = wid >> 1;      // 0..3 : M strip of 32
    const int wc   = wid & 1;       // 0..1 : N strip of 112

    const int bx = blockIdx.x;      // text pair -> batches 2bx, 2bx+1
    const int b2 = blockIdx.y;      // image batch
    const __half* At = g_txt + (size_t)bx * (2 * TT * DD);
    const __half* Bt = g_img + (size_t)b2 * (II * DD);

    // zero B pad rows (196..223) in all stages
    {
        uint4 z = make_uint4(0, 0, 0, 0);
        for (int u = tid; u < 28 * 8; u += 256) {
            int row = 196 + (u >> 3), seg = u & 7;
            uint32_t o = swz(row, seg * 16);
            #pragma unroll
            for (int st = 0; st < N_STAGE; st++)
                *(uint4*)(smem + st * STAGE_SZ + B_T + o) = z;
        }
    }
    __syncthreads();

    issue_stage(sb,                At, Bt, 0,   tid); CP_COMMIT();
    issue_stage(sb + STAGE_SZ,     At, Bt, 64,  tid); CP_COMMIT();
    issue_stage(sb + 2 * STAGE_SZ, At, Bt, 128, tid); CP_COMMIT();

    float c[112];
    #pragma unroll
    for (int i = 0; i < 112; i++) c[i] = 0.0f;

    #pragma unroll 1
    for (int ck = 0; ck < 8; ck++) {
        if (ck < 6) CP_WAIT2();
        else if (ck == 6) CP_WAIT1();
        else CP_WAIT0();
        __syncthreads();
        const uint32_t stg = sb + (uint32_t)(ck % 3) * STAGE_SZ;
        compute_chunk(stg, c, wr, wc, lane);
        __syncthreads();
        if (ck + 3 <= 7) {
            issue_stage(stg, At, Bt, (ck + 3) * 64, tid);
            CP_COMMIT();
        }
    }

    // ---------------- epilogue: masked row-max, then mean over tokens -------
    float* red = (float*)smem;      // [2][128] then [128] scratch
    #pragma unroll
    for (int mt = 0; mt < 2; mt++) {
        float m0 = -3.0e38f, m1 = -3.0e38f;
        #pragma unroll
        for (int nt = 0; nt < 14; nt++) {
            const float* acc = c + (mt * 14 + nt) * 4;
            int i0 = wc * 112 + nt * 8 + 2 * (lane & 3);
            if (i0 < II)     { m0 = fmaxf(m0, acc[0]); m1 = fmaxf(m1, acc[2]); }
            if (i0 + 1 < II) { m0 = fmaxf(m0, acc[1]); m1 = fmaxf(m1, acc[3]); }
        }
        #pragma unroll
        for (int o = 1; o <= 2; o <<= 1) {
            m0 = fmaxf(m0, __shfl_xor_sync(0xffffffffu, m0, o));
            m1 = fmaxf(m1, __shfl_xor_sync(0xffffffffu, m1, o));
        }
        if ((lane & 3) == 0) {
            int t = wr * 32 + mt * 16 + (lane >> 2);
            red[wc * 128 + t]     = m0;
            red[wc * 128 + t + 8] = m1;
        }
    }
    __syncthreads();
    float* red2 = red + 256;
    if (tid < 128) red2[tid] = fmaxf(red[tid], red[128 + tid]);
    __syncthreads();
    if (wid < 2) {
        float v = red2[wid * 64 + lane] + red2[wid * 64 + 32 + lane];
        #pragma unroll
        for (int o = 16; o >= 1; o >>= 1) v += __shfl_xor_sync(0xffffffffu, v, o);
        if (lane == 0) g_S[(2 * bx + wid) * BB + b2] = v * (1.0f / 64.0f);
    }
}

// ---------------- loss kernel ----------------------------------------------
__global__ __launch_bounds__(256)
void loss_kernel(float* __restrict__ out)
{
    extern __shared__ float sh[];                 // [128][129]
    __shared__ float ws[8];
    const int tid = threadIdx.x;
    const float invT = 1.0f / 0.07f;

    for (int i = tid; i < BB * 32; i += 256) {
        int b = i >> 5, j4 = i & 31;
        float4 v = reinterpret_cast<const float4*>(g_S)[b * 32 + j4];
        float* row = sh + b * 129 + j4 * 4;
        row[0] = v.x; row[1] = v.y; row[2] = v.z; row[3] = v.w;
    }
    __syncthreads();

    const int b = tid & 127;
    const bool isCol = tid >= 128;
    float mx = -3.0e38f;
    #pragma unroll 4
    for (int j = 0; j < BB; j++) {
        float v = (isCol ? sh[j * 129 + b] : sh[b * 129 + j]) * invT;
        mx = fmaxf(mx, v);
    }
    float s = 0.0f;
    #pragma unroll 4
    for (int j = 0; j < BB; j++) {
        float v = (isCol ? sh[j * 129 + b] : sh[b * 129 + j]) * invT;
        s += __expf(v - mx);
    }
    float lse = mx + __logf(s);
    float part = 0.5f * lse;
    if (!isCol) part -= sh[b * 129 + b] * invT;

    #pragma unroll
    for (int o = 16; o >= 1; o >>= 1) part += __shfl_xor_sync(0xffffffffu, part, o);
    if ((tid & 31) == 0) ws[tid >> 5] = part;
    __syncthreads();
    if (tid == 0) {
        float t = 0.0f;
        #pragma unroll
        for (int w = 0; w < 8; w++) t += ws[w];
        out[0] = t * (1.0f / BB);
    }
}

// ---------------- launch ----------------------------------------------------
extern "C" void kernel_launch(void* const* d_in, const int* in_sizes, int n_in,
                              void* d_out, int out_size)
{
    const float* a0 = (const float*)d_in[0];
    const float* a1 = (const float*)d_in[1];
    const float *img, *txt;
    if (in_sizes[0] == BB * II * DD) { img = a0; txt = a1; }
    else                             { img = a1; txt = a0; }

    cudaFuncSetAttribute(maxsim_mma_kernel,
                         cudaFuncAttributeMaxDynamicSharedMemorySize, SMEM_TOTAL);
    cudaFuncSetAttribute(loss_kernel,
                         cudaFuncAttributeMaxDynamicSharedMemorySize, 129 * 128 * 4);

    __half *th, *ih;
    cudaGetSymbolAddress((void**)&th, g_txt);
    cudaGetSymbolAddress((void**)&ih, g_img);

    const int nt4 = BB * TT * DD / 4;
    const int ni4 = BB * II * DD / 4;
    round_kernel<<<(nt4 + 255) / 256, 256>>>(txt, th, nt4);
    round_kernel<<<(ni4 + 255) / 256, 256>>>(img, ih, ni4);

    dim3 grid(BB / 2, BB);   // 64 x 128
    maxsim_mma_kernel<<<grid, 256, SMEM_TOTAL>>>();

    loss_kernel<<<1, 256, 129 * 128 * 4>>>((float*)d_out);
}

// round 8
// speedup vs baseline: 9.2667x; 1.1954x over previous
#include <cuda_runtime.h>
#include <cuda_fp16.h>
#include <cstdint>

#define BB 128
#define TT 64
#define II 196
#define DD 512

// ---------------- scratch --------------------------------------------------
__device__ __align__(16) __half g_txt[BB * TT * DD];
__device__ __align__(16) __half g_img[BB * II * DD];
__device__ float g_S[BB * BB];

// ---------------- stage layout (bytes); K-chunk = 64 halves = 128 B/row ----
// A: 64 rows x 128B = 8192 ; B: 208 rows x 128B = 26624
#define A_T  0
#define B_T  8192
#define STAGE_SZ 34816
#define N_STAGE 3
#define SMEM_TOTAL (N_STAGE * STAGE_SZ + 2048)   // 106496 -> 2 CTAs/SM

// ---------------- PTX helpers ----------------------------------------------
__device__ __forceinline__ uint32_t smem_u32(const void* p) {
    uint32_t a;
    asm("{ .reg .u64 t; cvta.to.shared.u64 t, %1; cvt.u32.u64 %0, t; }"
        : "=r"(a) : "l"(p));
    return a;
}
__device__ __forceinline__ void cp16(uint32_t dst, const void* src) {
    asm volatile("cp.async.cg.shared.global [%0], [%1], 16;"
                 :: "r"(dst), "l"(src) : "memory");
}
#define CP_COMMIT() asm volatile("cp.async.commit_group;" ::: "memory")
#define CP_WAIT2()  asm volatile("cp.async.wait_group 2;" ::: "memory")
#define CP_WAIT1()  asm volatile("cp.async.wait_group 1;" ::: "memory")
#define CP_WAIT0()  asm volatile("cp.async.wait_group 0;" ::: "memory")

__device__ __forceinline__ void ldsm4(uint32_t* r, uint32_t addr) {
    asm volatile("ldmatrix.sync.aligned.m8n8.x4.shared.b16 {%0,%1,%2,%3}, [%4];"
                 : "=r"(r[0]), "=r"(r[1]), "=r"(r[2]), "=r"(r[3]) : "r"(addr));
}
__device__ __forceinline__ void mma_f16(float* c, const uint32_t* a, const uint32_t* b) {
    asm volatile("mma.sync.aligned.m16n8k16.row.col.f32.f16.f16.f32 "
                 "{%0,%1,%2,%3}, {%4,%5,%6,%7}, {%8,%9}, {%0,%1,%2,%3};"
                 : "+f"(c[0]), "+f"(c[1]), "+f"(c[2]), "+f"(c[3])
                 : "r"(a[0]), "r"(a[1]), "r"(a[2]), "r"(a[3]),
                   "r"(b[0]), "r"(b[1]));
}
__device__ __forceinline__ uint32_t swz(int row, uint32_t kb) {
    return (uint32_t)row * 128u + (kb ^ (uint32_t)((row & 7) << 4));
}

// ---------------- round kernel: fp32 -> fp16 --------------------------------
__global__ __launch_bounds__(256)
void round_kernel(const float* __restrict__ src, __half* __restrict__ dst, int n4)
{
    int i = blockIdx.x * 256 + threadIdx.x;
    if (i >= n4) return;
    float4 v = reinterpret_cast<const float4*>(src)[i];
    __half2 a(__float2half(v.x), __float2half(v.y));
    __half2 b(__float2half(v.z), __float2half(v.w));
    uint2 u;
    u.x = *(uint32_t*)&a; u.y = *(uint32_t*)&b;
    reinterpret_cast<uint2*>(dst)[i] = u;
}

// ---------------- stage loader (128 threads) --------------------------------
__device__ __forceinline__ void issue_stage(uint32_t sb,
    const __half* At, const __half* Bt, int k0, int tid)
{
    #pragma unroll
    for (int q = 0; q < 4; q++) {                 // A: 64 rows x 8 segs(16B)
        int u = tid + q * 128;
        int row = u >> 3, seg = u & 7;
        uint32_t o = swz(row, seg * 16);
        size_t g = (size_t)row * DD + k0 + seg * 8;
        cp16(sb + A_T + o, At + g);
    }
    #pragma unroll
    for (int q = 0; q < 13; q++) {                // B: 196 rows x 8 segs = 1568
        int u = tid + q * 128;
        if (u < II * 8) {
            int row = u >> 3, seg = u & 7;
            uint32_t o = swz(row, seg * 16);
            size_t g = (size_t)row * DD + k0 + seg * 8;
            cp16(sb + B_T + o, Bt + g);
        }
    }
}

// ---------------- per-chunk compute: 32x104 warp tile -----------------------
__device__ __forceinline__ void compute_chunk(uint32_t sb, float* c,
                                              int wr, int wc, int lane)
{
    const int rowA0 = wr * 32 + (lane & 15);
    const uint32_t kAh = (lane & 16) ? 16u : 0u;
    const int rowB0 = wc * 104 + ((lane & 16) ? 8 : 0) + (lane & 7);
    const uint32_t kBh = (lane & 8) ? 16u : 0u;

    #pragma unroll
    for (int s = 0; s < 4; s++) {
        uint32_t a[8];
        #pragma unroll
        for (int mt = 0; mt < 2; mt++) {
            uint32_t o = swz(rowA0 + mt * 16, s * 32 + kAh);
            ldsm4(a + 4 * mt, sb + A_T + o);
        }
        uint32_t b[28];
        #pragma unroll
        for (int p = 0; p < 7; p++) {             // covers 14 n8-tiles; use 13
            uint32_t o = swz(rowB0 + p * 16, s * 32 + kBh);
            ldsm4(b + 4 * p, sb + B_T + o);
        }
        #pragma unroll
        for (int mt = 0; mt < 2; mt++)
            #pragma unroll
            for (int nt = 0; nt < 13; nt++)
                mma_f16(c + (mt * 13 + nt) * 4, a + 4 * mt, b + 2 * nt);
    }
}

// ---------------- main maxsim kernel ----------------------------------------
__global__ __launch_bounds__(128, 2)
void maxsim_mma_kernel()
{
    extern __shared__ __align__(1024) char smem[];
    const uint32_t sb = smem_u32(smem);
    const int tid  = threadIdx.x;
    const int lane = tid & 31;
    const int wid  = tid >> 5;
    const int wr   = wid >> 1;      // 0..1 : M strip of 32
    const int wc   = wid & 1;       // 0..1 : N strip of 104

    const int b1 = blockIdx.x;      // text batch
    const int b2 = blockIdx.y;      // image batch
    const __half* At = g_txt + (size_t)b1 * (TT * DD);
    const __half* Bt = g_img + (size_t)b2 * (II * DD);

    // zero B pad rows (196..207) in all stages
    {
        uint4 z = make_uint4(0, 0, 0, 0);
        for (int u = tid; u < 12 * 8 * N_STAGE; u += 128) {
            int st = u / 96, v = u % 96;
            int row = 196 + (v >> 3), seg = v & 7;
            uint32_t o = swz(row, seg * 16);
            *(uint4*)(smem + st * STAGE_SZ + B_T + o) = z;
        }
    }
    __syncthreads();

    issue_stage(sb,                At, Bt, 0,   tid); CP_COMMIT();
    issue_stage(sb + STAGE_SZ,     At, Bt, 64,  tid); CP_COMMIT();
    issue_stage(sb + 2 * STAGE_SZ, At, Bt, 128, tid); CP_COMMIT();

    float c[104];
    #pragma unroll
    for (int i = 0; i < 104; i++) c[i] = 0.0f;

    #pragma unroll 1
    for (int ck = 0; ck < 8; ck++) {
        if (ck < 6) CP_WAIT2();
        else if (ck == 6) CP_WAIT1();
        else CP_WAIT0();
        __syncthreads();
        const uint32_t stg = sb + (uint32_t)(ck % 3) * STAGE_SZ;
        compute_chunk(stg, c, wr, wc, lane);
        __syncthreads();
        if (ck + 3 <= 7) {
            issue_stage(stg, At, Bt, (ck + 3) * 64, tid);
            CP_COMMIT();
        }
    }

    // ---------------- epilogue: masked row-max, then mean over tokens -------
    float* red = (float*)smem;      // [2][64] then [64] scratch
    #pragma unroll
    for (int mt = 0; mt < 2; mt++) {
        float m0 = -3.0e38f, m1 = -3.0e38f;
        #pragma unroll
        for (int nt = 0; nt < 13; nt++) {
            const float* acc = c + (mt * 13 + nt) * 4;
            int i0 = wc * 104 + nt * 8 + 2 * (lane & 3);
            if (i0 < II)     { m0 = fmaxf(m0, acc[0]); m1 = fmaxf(m1, acc[2]); }
            if (i0 + 1 < II) { m0 = fmaxf(m0, acc[1]); m1 = fmaxf(m1, acc[3]); }
        }
        #pragma unroll
        for (int o = 1; o <= 2; o <<= 1) {
            m0 = fmaxf(m0, __shfl_xor_sync(0xffffffffu, m0, o));
            m1 = fmaxf(m1, __shfl_xor_sync(0xffffffffu, m1, o));
        }
        if ((lane & 3) == 0) {
            int t = wr * 32 + mt * 16 + (lane >> 2);
            red[wc * 64 + t]     = m0;
            red[wc * 64 + t + 8] = m1;
        }
    }
    __syncthreads();
    float* red2 = red + 128;
    if (tid < 64) red2[tid] = fmaxf(red[tid], red[64 + tid]);
    __syncthreads();
    if (wid == 0) {
        float v = red2[lane] + red2[lane + 32];
        #pragma unroll
        for (int o = 16; o >= 1; o >>= 1) v += __shfl_xor_sync(0xffffffffu, v, o);
        if (lane == 0) g_S[b1 * BB + b2] = v * (1.0f / 64.0f);
    }
}

// ---------------- loss kernel ----------------------------------------------
__global__ __launch_bounds__(256)
void loss_kernel(float* __restrict__ out)
{
    extern __shared__ float sh[];                 // [128][129]
    __shared__ float ws[8];
    const int tid = threadIdx.x;
    const float invT = 1.0f / 0.07f;

    for (int i = tid; i < BB * 32; i += 256) {
        int b = i >> 5, j4 = i & 31;
        float4 v = reinterpret_cast<const float4*>(g_S)[b * 32 + j4];
        float* row = sh + b * 129 + j4 * 4;
        row[0] = v.x; row[1] = v.y; row[2] = v.z; row[3] = v.w;
    }
    __syncthreads();

    const int b = tid & 127;
    const bool isCol = tid >= 128;
    float mx = -3.0e38f;
    #pragma unroll 4
    for (int j = 0; j < BB; j++) {
        float v = (isCol ? sh[j * 129 + b] : sh[b * 129 + j]) * invT;
        mx = fmaxf(mx, v);
    }
    float s = 0.0f;
    #pragma unroll 4
    for (int j = 0; j < BB; j++) {
        float v = (isCol ? sh[j * 129 + b] : sh[b * 129 + j]) * invT;
        s += __expf(v - mx);
    }
    float lse = mx + __logf(s);
    float part = 0.5f * lse;
    if (!isCol) part -= sh[b * 129 + b] * invT;

    #pragma unroll
    for (int o = 16; o >= 1; o >>= 1) part += __shfl_xor_sync(0xffffffffu, part, o);
    if ((tid & 31) == 0) ws[tid >> 5] = part;
    __syncthreads();
    if (tid == 0) {
        float t = 0.0f;
        #pragma unroll
        for (int w = 0; w < 8; w++) t += ws[w];
        out[0] = t * (1.0f / BB);
    }
}

// ---------------- launch ----------------------------------------------------
extern "C" void kernel_launch(void* const* d_in, const int* in_sizes, int n_in,
                              void* d_out, int out_size)
{
    const float* a0 = (const float*)d_in[0];
    const float* a1 = (const float*)d_in[1];
    const float *img, *txt;
    if (in_sizes[0] == BB * II * DD) { img = a0; txt = a1; }
    else                             { img = a1; txt = a0; }

    cudaFuncSetAttribute(maxsim_mma_kernel,
                         cudaFuncAttributeMaxDynamicSharedMemorySize, SMEM_TOTAL);
    cudaFuncSetAttribute(loss_kernel,
                         cudaFuncAttributeMaxDynamicSharedMemorySize, 129 * 128 * 4);

    __half *th, *ih;
    cudaGetSymbolAddress((void**)&th, g_txt);
    cudaGetSymbolAddress((void**)&ih, g_img);

    const int nt4 = BB * TT * DD / 4;
    const int ni4 = BB * II * DD / 4;
    round_kernel<<<(nt4 + 255) / 256, 256>>>(txt, th, nt4);
    round_kernel<<<(ni4 + 255) / 256, 256>>>(img, ih, ni4);

    dim3 grid(BB, BB);   // 128 x 128
    maxsim_mma_kernel<<<grid, 128, SMEM_TOTAL>>>();

    loss_kernel<<<1, 256, 129 * 128 * 4>>>((float*)d_out);
}